// round 16
// baseline (speedup 1.0000x reference)
#include <cuda_runtime.h>
#include <cuda_bf16.h>
#include <cuda_fp16.h>
#include <cstdint>

#define NB 8
#define NN 4096
#define NM 1024
#define ND 256

static constexpr size_t OFF_WHT = 0;
static constexpr size_t OFF_WLT = OFF_WHT + (size_t)ND * ND;
static constexpr size_t OFF_WGT = OFF_WLT + (size_t)ND * ND;
static constexpr size_t OFF_BLG = OFF_WGT + (size_t)ND * ND;
static constexpr size_t OFF_HHI = OFF_BLG + 512;
static constexpr size_t OFF_HLO = OFF_HHI + (size_t)NB * NN * ND / 2;
static constexpr size_t OFF_LHI = OFF_HLO + (size_t)NB * NN * ND / 2;
static constexpr size_t OFF_LLO = OFF_LHI + (size_t)NB * NM * ND / 2;
static constexpr size_t OFF_G   = OFF_LLO + (size_t)NB * NM * ND / 2;
static constexpr size_t OFF_GT  = OFF_G   + (size_t)NB * NM * ND;
static constexpr size_t SCRATCH_TOTAL = OFF_GT + (size_t)NB * ND * NM / 2;

__device__ float g_scratch[SCRATCH_TOTAL];

__device__ __forceinline__ uint32_t pack_bf(float x, float y) {
    __nv_bfloat162 t = __floats2bfloat162_rn(x, y);
    return *(uint32_t*)&t;
}
__device__ __forceinline__ uint32_t pack_hf(float x, float y) {
    __half2 t = __floats2half2_rn(x, y);
    return *(uint32_t*)&t;
}
__device__ __forceinline__ float bf_res(float x) {
    return x - __bfloat162float(__float2bfloat16_rn(x));
}
__device__ __forceinline__ void cp16(uint32_t dst, const void* src) {
    asm volatile("cp.async.cg.shared.global [%0], [%1], 16;" :: "r"(dst), "l"(src));
}

#define MMA16B(d, a, b)                                                        \
    asm volatile(                                                              \
        "mma.sync.aligned.m16n8k16.row.col.f32.bf16.bf16.f32 "                 \
        "{%0,%1,%2,%3},{%4,%5,%6,%7},{%8,%9},{%0,%1,%2,%3};\n"                 \
        : "+f"((d)[0]), "+f"((d)[1]), "+f"((d)[2]), "+f"((d)[3])               \
        : "r"((a)[0]), "r"((a)[1]), "r"((a)[2]), "r"((a)[3]),                  \
          "r"((b)[0]), "r"((b)[1]))

#define MMA16H(d, a, b)                                                        \
    asm volatile(                                                              \
        "mma.sync.aligned.m16n8k16.row.col.f32.f16.f16.f32 "                   \
        "{%0,%1,%2,%3},{%4,%5,%6,%7},{%8,%9},{%0,%1,%2,%3};\n"                 \
        : "+f"((d)[0]), "+f"((d)[1]), "+f"((d)[2]), "+f"((d)[3])               \
        : "r"((a)[0]), "r"((a)[1]), "r"((a)[2]), "r"((a)[3]),                  \
          "r"((b)[0]), "r"((b)[1]))

__global__ void transpose_w_k(const float* __restrict__ Wh, const float* __restrict__ Wl,
                              const float* __restrict__ Wg, const float* __restrict__ bl,
                              const float* __restrict__ bg, float* __restrict__ wht,
                              float* __restrict__ wlt, float* __restrict__ wgt,
                              float* __restrict__ blg) {
    int i = blockIdx.x * blockDim.x + threadIdx.x;
    int n = i >> 8, k = i & 255;
    wht[i] = Wh[k * ND + n];
    wlt[i] = Wl[k * ND + n];
    wgt[i] = Wg[k * ND + n];
    if (i < 512) blg[i] = (i < 256) ? bl[i] : bg[i - 256];
}

__global__ void transpose_g_k(const float* __restrict__ G, __half* __restrict__ GT) {
    __shared__ float t[32][33];
    int b = blockIdx.z;
    int m0 = blockIdx.x * 32, d0 = blockIdx.y * 32;
    const float* src = G + (size_t)b * NM * ND;
    __half* dst = GT + (size_t)b * ND * NM;
    int x = threadIdx.x, y = threadIdx.y;
#pragma unroll
    for (int i = 0; i < 32; i += 8) t[y + i][x] = src[(size_t)(m0 + y + i) * ND + d0 + x];
    __syncthreads();
#pragma unroll
    for (int i = 0; i < 32; i += 8)
        dst[(size_t)(d0 + y + i) * NM + m0 + x] = __float2half_rn(t[x][y + i]);
}

// ---------------- bf16x3 TT GEMM (validated R15), packing epilogue ----------------
template <int OUT, bool SCALE>
__global__ void __launch_bounds__(256)
gemm_bf3(const float* __restrict__ Aptr, const float* __restrict__ Bptr,
         const float* __restrict__ bias,
         uint32_t* __restrict__ Chi, uint32_t* __restrict__ Clo,
         float* __restrict__ Cg, int K, int Ncols) {
    constexpr int BM = 128, BK = 32, LDSR = 20;
    constexpr int ARR = BM * LDSR;
    extern __shared__ uint32_t sm[];
    uint32_t* As = sm;
    uint32_t* Bs = sm + ARR;
    uint32_t* Al = sm + 2 * ARR;
    uint32_t* Bl = sm + 3 * ARR;

    int tid = threadIdx.x;
    int lane = tid & 31, wid = tid >> 5;
    int wm = wid >> 1, wn = wid & 1;
    int grp = lane >> 2, tq = lane & 3;

    const float* A = Aptr + (long long)blockIdx.x * BM * K;
    const float* Bm = Bptr + (long long)blockIdx.y * 128 * K;

    float acc[2][8][4];
#pragma unroll
    for (int i = 0; i < 2; i++)
#pragma unroll
        for (int j = 0; j < 8; j++)
#pragma unroll
            for (int q = 0; q < 4; q++) acc[i][j][q] = 0.f;

    for (int kc = 0; kc < K; kc += BK) {
        __syncthreads();
#pragma unroll
        for (int it = 0; it < 4; it++) {
            int idx = tid + it * 256;
            int rr = idx >> 3, cc = (idx & 7) * 4;
            int pc = cc >> 1;
            float4 va = *(const float4*)(A + (long long)rr * K + kc + cc);
            float4 vb = *(const float4*)(Bm + (long long)rr * K + kc + cc);
            As[rr * LDSR + pc]     = pack_bf(va.x, va.y);
            As[rr * LDSR + pc + 1] = pack_bf(va.z, va.w);
            Al[rr * LDSR + pc]     = pack_bf(bf_res(va.x), bf_res(va.y));
            Al[rr * LDSR + pc + 1] = pack_bf(bf_res(va.z), bf_res(va.w));
            Bs[rr * LDSR + pc]     = pack_bf(vb.x, vb.y);
            Bs[rr * LDSR + pc + 1] = pack_bf(vb.z, vb.w);
            Bl[rr * LDSR + pc]     = pack_bf(bf_res(vb.x), bf_res(vb.y));
            Bl[rr * LDSR + pc + 1] = pack_bf(bf_res(vb.z), bf_res(vb.w));
        }
        __syncthreads();
#pragma unroll
        for (int ks = 0; ks < 2; ks++) {
            int kp = ks * 8;
            uint32_t a[2][4], al[2][4];
#pragma unroll
            for (int i = 0; i < 2; i++) {
                int ro = (wm * 32 + i * 16 + grp) * LDSR + kp + tq;
                a[i][0] = As[ro];
                a[i][1] = As[ro + 8 * LDSR];
                a[i][2] = As[ro + 4];
                a[i][3] = As[ro + 8 * LDSR + 4];
                al[i][0] = Al[ro];
                al[i][1] = Al[ro + 8 * LDSR];
                al[i][2] = Al[ro + 4];
                al[i][3] = Al[ro + 8 * LDSR + 4];
            }
#pragma unroll
            for (int j = 0; j < 8; j++) {
                int co = (wn * 64 + j * 8 + grp) * LDSR + kp + tq;
                uint32_t b[2], bl2[2];
                b[0] = Bs[co];
                b[1] = Bs[co + 4];
                bl2[0] = Bl[co];
                bl2[1] = Bl[co + 4];
#pragma unroll
                for (int i = 0; i < 2; i++) {
                    MMA16B(acc[i][j], al[i], b);
                    MMA16B(acc[i][j], a[i], bl2);
                    MMA16B(acc[i][j], a[i], b);
                }
            }
        }
    }

    const float SC = SCALE ? 1.4426950408889634f : 1.0f;  // log2(e) for softmax folding
    int row0 = blockIdx.x * BM + wm * 32 + grp;
    int col0 = blockIdx.y * 128 + wn * 64 + 2 * tq;
#pragma unroll
    for (int i = 0; i < 2; i++) {
#pragma unroll
        for (int j = 0; j < 8; j++) {
            int row = row0 + i * 16;
            int col = col0 + j * 8;
            float2 bb = *(const float2*)(bias + col);
            float2 v0 = make_float2((acc[i][j][0] + bb.x) * SC, (acc[i][j][1] + bb.y) * SC);
            float2 v1 = make_float2((acc[i][j][2] + bb.x) * SC, (acc[i][j][3] + bb.y) * SC);
            if (OUT == 1 || (OUT == 2 && col < 256)) {
                int pr = (OUT == 1) ? (Ncols >> 1) : 128;
                long long i0 = (long long)row * pr + (col >> 1);
                long long i1 = (long long)(row + 8) * pr + (col >> 1);
                Chi[i0] = pack_bf(v0.x, v0.y);
                Clo[i0] = pack_bf(bf_res(v0.x), bf_res(v0.y));
                Chi[i1] = pack_bf(v1.x, v1.y);
                Clo[i1] = pack_bf(bf_res(v1.x), bf_res(v1.y));
            } else {
                int gc = col - 256;
                *(float2*)(Cg + (long long)row * 256 + gc) = v0;
                *(float2*)(Cg + (long long)(row + 8) * 256 + gc) = v1;
            }
        }
    }
}

// ---------------- fused scores+softmax+out (R15 skeleton, 3-stage pipeline) -----------
__global__ void __launch_bounds__(256, 1)
fused_attn(const uint32_t* __restrict__ Hhi, const uint32_t* __restrict__ Hlo,
           const uint32_t* __restrict__ Lhi, const uint32_t* __restrict__ Llo,
           const uint32_t* __restrict__ Gt,  // fp16 pairs [B,256,512] u32
           const float* __restrict__ p, float* __restrict__ out) {
    constexpr int LDSR = 20, ARR = 128 * LDSR, STAGE = 4 * ARR;
    constexpr int NSTG = 3;
    constexpr int LDG = 68;
    extern __shared__ uint32_t sm[];
    uint32_t* sG = sm + NSTG * STAGE;
    uint32_t sbase = (uint32_t)__cvta_generic_to_shared(sm);
    uint32_t gbase = sbase + NSTG * STAGE * 4;

    int tid = threadIdx.x;
    int lane = tid & 31, wid = tid >> 5;
    int grp = lane >> 2, tq = lane & 3;
    int bx = blockIdx.x, zb = blockIdx.z;

    const uint32_t* Ah = Hhi + ((long long)zb * NN + bx * 128) * 128;
    const uint32_t* Alg = Hlo + ((long long)zb * NN + bx * 128) * 128;
    const uint32_t* Bh_b = Lhi + (long long)zb * NM * 128;
    const uint32_t* Bl_b = Llo + (long long)zb * NM * 128;
    const uint32_t* Gtb = Gt + (long long)zb * 256 * 512;

    int rr0 = tid >> 2, uc0 = (tid & 3) * 4;
    int rr1 = (tid + 256) >> 2, uc1 = ((tid + 256) & 3) * 4;

    float o[32][4];
#pragma unroll
    for (int j = 0; j < 32; j++)
#pragma unroll
        for (int q = 0; q < 4; q++) o[j][q] = 0.f;
    float m0 = -1e30f, m1 = -1e30f, s0 = 0.f, s1 = 0.f;

    for (int mt = 0; mt < 8; mt++) {
        const uint32_t* Bh = Bh_b + (long long)mt * 128 * 128;
        const uint32_t* Bl = Bl_b + (long long)mt * 128 * 128;

        auto issue = [&](int st, int kcp, int ch) {
            uint32_t dA = sbase + (uint32_t)st * STAGE * 4;
            uint32_t dB = dA + ARR * 4;
            uint32_t dAl = dA + 2 * ARR * 4;
            uint32_t dBl = dA + 3 * ARR * 4;
            uint32_t o0 = (uint32_t)(rr0 * LDSR + uc0) * 4;
            uint32_t o1 = (uint32_t)(rr1 * LDSR + uc1) * 4;
            cp16(dA + o0, Ah + (long long)rr0 * 128 + kcp + uc0);
            cp16(dA + o1, Ah + (long long)rr1 * 128 + kcp + uc1);
            cp16(dAl + o0, Alg + (long long)rr0 * 128 + kcp + uc0);
            cp16(dAl + o1, Alg + (long long)rr1 * 128 + kcp + uc1);
            cp16(dB + o0, Bh + (long long)rr0 * 128 + kcp + uc0);
            cp16(dB + o1, Bh + (long long)rr1 * 128 + kcp + uc1);
            cp16(dBl + o0, Bl + (long long)rr0 * 128 + kcp + uc0);
            cp16(dBl + o1, Bl + (long long)rr1 * 128 + kcp + uc1);
            int g = ch * 512 + tid * 2;
            int gr = g >> 4, gc = (g & 15) * 4;
            cp16(gbase + (uint32_t)(gr * LDG + gc) * 4, Gtb + (long long)gr * 512 + mt * 64 + gc);
            g++; gr = g >> 4; gc = (g & 15) * 4;
            cp16(gbase + (uint32_t)(gr * LDG + gc) * 4, Gtb + (long long)gr * 512 + mt * 64 + gc);
            asm volatile("cp.async.commit_group;");
        };

        float c[16][4];
#pragma unroll
        for (int j = 0; j < 16; j++)
#pragma unroll
            for (int q = 0; q < 4; q++) c[j][q] = 0.f;

        // phase A: scores, 3-stage cp.async pipeline (two tiles of load slack)
        issue(0, 0, 0);
        issue(1, 16, 1);
        for (int t = 0; t < 8; t++) {
            if (t < 7) {
                asm volatile("cp.async.wait_group 1;");
            } else {
                asm volatile("cp.async.wait_group 0;");
            }
            __syncthreads();
            const uint32_t* As = sm + (t % NSTG) * STAGE;
            const uint32_t* Bs = As + ARR;
            const uint32_t* Al = As + 2 * ARR;
            const uint32_t* Blo2 = As + 3 * ARR;
#pragma unroll
            for (int ks = 0; ks < 2; ks++) {
                int kp = ks * 8;
                uint32_t a[4], al[4];
                int ro = (wid * 16 + grp) * LDSR + kp + tq;
                a[0] = As[ro];
                a[1] = As[ro + 8 * LDSR];
                a[2] = As[ro + 4];
                a[3] = As[ro + 8 * LDSR + 4];
                al[0] = Al[ro];
                al[1] = Al[ro + 8 * LDSR];
                al[2] = Al[ro + 4];
                al[3] = Al[ro + 8 * LDSR + 4];
#pragma unroll
                for (int j = 0; j < 16; j++) {
                    int co = (j * 8 + grp) * LDSR + kp + tq;
                    uint32_t b[2], bl2[2];
                    b[0] = Bs[co];
                    b[1] = Bs[co + 4];
                    bl2[0] = Blo2[co];
                    bl2[1] = Blo2[co + 4];
                    MMA16B(c[j], al, b);
                    MMA16B(c[j], a, bl2);
                    MMA16B(c[j], a, b);
                }
            }
            if (t + 2 < 8) issue((t + 2) % NSTG, (t + 2) * 16, t + 2);
        }

        // phase B: online softmax (quad-local), exp2 domain
        float mx0 = -1e30f, mx1 = -1e30f;
#pragma unroll
        for (int j = 0; j < 16; j++) {
            mx0 = fmaxf(mx0, fmaxf(c[j][0], c[j][1]));
            mx1 = fmaxf(mx1, fmaxf(c[j][2], c[j][3]));
        }
        mx0 = fmaxf(mx0, __shfl_xor_sync(0xffffffffu, mx0, 1));
        mx0 = fmaxf(mx0, __shfl_xor_sync(0xffffffffu, mx0, 2));
        mx1 = fmaxf(mx1, __shfl_xor_sync(0xffffffffu, mx1, 1));
        mx1 = fmaxf(mx1, __shfl_xor_sync(0xffffffffu, mx1, 2));
        float nm0 = fmaxf(m0, mx0), nm1 = fmaxf(m1, mx1);
        float sc0 = exp2f(m0 - nm0), sc1 = exp2f(m1 - nm1);
        m0 = nm0; m1 = nm1;
        s0 *= sc0; s1 *= sc1;
        if (sc0 != 1.0f || sc1 != 1.0f) {
#pragma unroll
            for (int j = 0; j < 32; j++) {
                o[j][0] *= sc0; o[j][1] *= sc0;
                o[j][2] *= sc1; o[j][3] *= sc1;
            }
        }
#pragma unroll
        for (int j = 0; j < 16; j++) {
            c[j][0] = exp2f(c[j][0] - m0);
            c[j][1] = exp2f(c[j][1] - m0);
            c[j][2] = exp2f(c[j][2] - m1);
            c[j][3] = exp2f(c[j][3] - m1);
            s0 += c[j][0] + c[j][1];
            s1 += c[j][2] + c[j][3];
        }

        // phase C: out += attn @ GT (attn from registers)
#pragma unroll
        for (int kt = 0; kt < 8; kt++) {
            uint32_t a[4];
            a[0] = pack_hf(c[2 * kt][0], c[2 * kt][1]);
            a[1] = pack_hf(c[2 * kt][2], c[2 * kt][3]);
            a[2] = pack_hf(c[2 * kt + 1][0], c[2 * kt + 1][1]);
            a[3] = pack_hf(c[2 * kt + 1][2], c[2 * kt + 1][3]);
#pragma unroll
            for (int j = 0; j < 32; j++) {
                int co = (j * 8 + grp) * LDG + kt * 8 + tq;
                uint32_t b[2];
                b[0] = sG[co];
                b[1] = sG[co + 4];
                MMA16H(o[j], a, b);
            }
        }
        __syncthreads();  // stages/sG stable before next tile's copies
    }

    // epilogue: normalize, residual, store
    s0 += __shfl_xor_sync(0xffffffffu, s0, 1);
    s0 += __shfl_xor_sync(0xffffffffu, s0, 2);
    s1 += __shfl_xor_sync(0xffffffffu, s1, 1);
    s1 += __shfl_xor_sync(0xffffffffu, s1, 2);
    float inv0 = 1.0f / s0, inv1 = 1.0f / s1;

    int r0 = bx * 128 + wid * 16 + grp;
    float* ob = out + ((long long)zb * NN + r0) * ND;
    const float* pb = p + ((long long)zb * NN + r0) * ND;
#pragma unroll
    for (int j = 0; j < 32; j++) {
        int col = j * 8 + 2 * tq;
        float2 v0 = make_float2(o[j][0] * inv0 + pb[col], o[j][1] * inv0 + pb[col + 1]);
        float2 v1 = make_float2(o[j][2] * inv1 + pb[8 * ND + col],
                                o[j][3] * inv1 + pb[8 * ND + col + 1]);
        *(float2*)(ob + col) = v0;
        *(float2*)(ob + 8 * ND + col) = v1;
    }
}

extern "C" void kernel_launch(void* const* d_in, const int* in_sizes, int n_in,
                              void* d_out, int out_size) {
    const float* p  = (const float*)d_in[0];
    const float* r  = (const float*)d_in[1];
    const float* Wh = (const float*)d_in[3];
    const float* bh = (const float*)d_in[4];
    const float* Wl = (const float*)d_in[5];
    const float* bl = (const float*)d_in[6];
    const float* Wg = (const float*)d_in[7];
    const float* bg = (const float*)d_in[8];
    float* out = (float*)d_out;
    (void)in_sizes; (void)n_in; (void)out_size;

    float* s = nullptr;
    cudaGetSymbolAddress((void**)&s, g_scratch);
    float* WhT = s + OFF_WHT;
    float* WlT = s + OFF_WLT;
    float* BLG = s + OFF_BLG;
    uint32_t* Hhi = (uint32_t*)(s + OFF_HHI);
    uint32_t* Hlo = (uint32_t*)(s + OFF_HLO);
    uint32_t* Lhi = (uint32_t*)(s + OFF_LHI);
    uint32_t* Llo = (uint32_t*)(s + OFF_LLO);
    float* G = s + OFF_G;
    __half* GTh = (__half*)(s + OFF_GT);

    const int SMEM_BF3 = 4 * 128 * 20 * 4;                       // 40960
    const int SMEM_FUSED = 3 * 4 * 128 * 20 * 4 + 256 * 68 * 4;  // 122880 + 69632 = 192512
    cudaFuncSetAttribute(gemm_bf3<1, true>,
                         cudaFuncAttributeMaxDynamicSharedMemorySize, SMEM_BF3);
    cudaFuncSetAttribute(gemm_bf3<2, false>,
                         cudaFuncAttributeMaxDynamicSharedMemorySize, SMEM_BF3);
    cudaFuncSetAttribute(fused_attn,
                         cudaFuncAttributeMaxDynamicSharedMemorySize, SMEM_FUSED);

    // 0. transpose weights; concat biases
    transpose_w_k<<<256, 256>>>(Wh, Wl, Wg, bl, bg, WhT, WlT, WlT + (size_t)ND * ND, BLG);

    // 1. H = (p @ Wh + bh) * log2(e)  -> packed bf16 hi/lo
    gemm_bf3<1, true><<<dim3(NB * NN / 128, ND / 128, 1), 256, SMEM_BF3>>>(
        p, WhT, bh, Hhi, Hlo, nullptr, ND, ND);

    // 2+3. [L | G] = r @ [Wl | Wg] + [bl | bg]  (L packed bf16, G fp32)
    gemm_bf3<2, false><<<dim3(NB * NM / 128, 2 * ND / 128, 1), 256, SMEM_BF3>>>(
        r, WlT, BLG, Lhi, Llo, G, ND, 2 * ND);

    // 4. GT[b][d][m] fp16
    transpose_g_k<<<dim3(NM / 32, ND / 32, NB), dim3(32, 8)>>>(G, GTh);

    // 5. fused: out = p + softmax2(H L^T) @ G
    fused_attn<<<dim3(NN / 128, 1, NB), 256, SMEM_FUSED>>>(
        Hhi, Hlo, Lhi, Llo, (const uint32_t*)GTh, p, out);
}

// round 17
// speedup vs baseline: 1.0453x; 1.0453x over previous
#include <cuda_runtime.h>
#include <cuda_bf16.h>
#include <cuda_fp16.h>
#include <cstdint>

#define NB 8
#define NN 4096
#define NM 1024
#define ND 256

static constexpr size_t OFF_WHT = 0;
static constexpr size_t OFF_WLT = OFF_WHT + (size_t)ND * ND;
static constexpr size_t OFF_WGT = OFF_WLT + (size_t)ND * ND;
static constexpr size_t OFF_BLG = OFF_WGT + (size_t)ND * ND;
static constexpr size_t OFF_HHI = OFF_BLG + 512;
static constexpr size_t OFF_HLO = OFF_HHI + (size_t)NB * NN * ND / 2;
static constexpr size_t OFF_LHI = OFF_HLO + (size_t)NB * NN * ND / 2;
static constexpr size_t OFF_LLO = OFF_LHI + (size_t)NB * NM * ND / 2;
static constexpr size_t OFF_G   = OFF_LLO + (size_t)NB * NM * ND / 2;
static constexpr size_t OFF_GT  = OFF_G   + (size_t)NB * NM * ND;
static constexpr size_t SCRATCH_TOTAL = OFF_GT + (size_t)NB * ND * NM / 2;

__device__ float g_scratch[SCRATCH_TOTAL];

__device__ __forceinline__ uint32_t pack_bf(float x, float y) {
    __nv_bfloat162 t = __floats2bfloat162_rn(x, y);
    return *(uint32_t*)&t;
}
__device__ __forceinline__ uint32_t pack_hf(float x, float y) {
    __half2 t = __floats2half2_rn(x, y);
    return *(uint32_t*)&t;
}
__device__ __forceinline__ float bf_res(float x) {
    return x - __bfloat162float(__float2bfloat16_rn(x));
}
__device__ __forceinline__ void cp16(uint32_t dst, const void* src) {
    asm volatile("cp.async.cg.shared.global [%0], [%1], 16;" :: "r"(dst), "l"(src));
}

#define MMA16B(d, a, b)                                                        \
    asm volatile(                                                              \
        "mma.sync.aligned.m16n8k16.row.col.f32.bf16.bf16.f32 "                 \
        "{%0,%1,%2,%3},{%4,%5,%6,%7},{%8,%9},{%0,%1,%2,%3};\n"                 \
        : "+f"((d)[0]), "+f"((d)[1]), "+f"((d)[2]), "+f"((d)[3])               \
        : "r"((a)[0]), "r"((a)[1]), "r"((a)[2]), "r"((a)[3]),                  \
          "r"((b)[0]), "r"((b)[1]))

#define MMA16H(d, a, b)                                                        \
    asm volatile(                                                              \
        "mma.sync.aligned.m16n8k16.row.col.f32.f16.f16.f32 "                   \
        "{%0,%1,%2,%3},{%4,%5,%6,%7},{%8,%9},{%0,%1,%2,%3};\n"                 \
        : "+f"((d)[0]), "+f"((d)[1]), "+f"((d)[2]), "+f"((d)[3])               \
        : "r"((a)[0]), "r"((a)[1]), "r"((a)[2]), "r"((a)[3]),                  \
          "r"((b)[0]), "r"((b)[1]))

__global__ void transpose_w_k(const float* __restrict__ Wh, const float* __restrict__ Wl,
                              const float* __restrict__ Wg, const float* __restrict__ bl,
                              const float* __restrict__ bg, float* __restrict__ wht,
                              float* __restrict__ wlt, float* __restrict__ wgt,
                              float* __restrict__ blg) {
    int i = blockIdx.x * blockDim.x + threadIdx.x;
    int n = i >> 8, k = i & 255;
    wht[i] = Wh[k * ND + n];
    wlt[i] = Wl[k * ND + n];
    wgt[i] = Wg[k * ND + n];
    if (i < 512) blg[i] = (i < 256) ? bl[i] : bg[i - 256];
}

__global__ void transpose_g_k(const float* __restrict__ G, __half* __restrict__ GT) {
    __shared__ float t[32][33];
    int b = blockIdx.z;
    int m0 = blockIdx.x * 32, d0 = blockIdx.y * 32;
    const float* src = G + (size_t)b * NM * ND;
    __half* dst = GT + (size_t)b * ND * NM;
    int x = threadIdx.x, y = threadIdx.y;
#pragma unroll
    for (int i = 0; i < 32; i += 8) t[y + i][x] = src[(size_t)(m0 + y + i) * ND + d0 + x];
    __syncthreads();
#pragma unroll
    for (int i = 0; i < 32; i += 8)
        dst[(size_t)(d0 + y + i) * NM + m0 + x] = __float2half_rn(t[x][y + i]);
}

// ---------------- bf16x3 TT GEMM (validated R15), packing epilogue ----------------
template <int OUT, bool SCALE>
__global__ void __launch_bounds__(256)
gemm_bf3(const float* __restrict__ Aptr, const float* __restrict__ Bptr,
         const float* __restrict__ bias,
         uint32_t* __restrict__ Chi, uint32_t* __restrict__ Clo,
         float* __restrict__ Cg, int K, int Ncols) {
    constexpr int BM = 128, BK = 32, LDSR = 20;
    constexpr int ARR = BM * LDSR;
    extern __shared__ uint32_t sm[];
    uint32_t* As = sm;
    uint32_t* Bs = sm + ARR;
    uint32_t* Al = sm + 2 * ARR;
    uint32_t* Bl = sm + 3 * ARR;

    int tid = threadIdx.x;
    int lane = tid & 31, wid = tid >> 5;
    int wm = wid >> 1, wn = wid & 1;
    int grp = lane >> 2, tq = lane & 3;

    const float* A = Aptr + (long long)blockIdx.x * BM * K;
    const float* Bm = Bptr + (long long)blockIdx.y * 128 * K;

    float acc[2][8][4];
#pragma unroll
    for (int i = 0; i < 2; i++)
#pragma unroll
        for (int j = 0; j < 8; j++)
#pragma unroll
            for (int q = 0; q < 4; q++) acc[i][j][q] = 0.f;

    for (int kc = 0; kc < K; kc += BK) {
        __syncthreads();
#pragma unroll
        for (int it = 0; it < 4; it++) {
            int idx = tid + it * 256;
            int rr = idx >> 3, cc = (idx & 7) * 4;
            int pc = cc >> 1;
            float4 va = *(const float4*)(A + (long long)rr * K + kc + cc);
            float4 vb = *(const float4*)(Bm + (long long)rr * K + kc + cc);
            As[rr * LDSR + pc]     = pack_bf(va.x, va.y);
            As[rr * LDSR + pc + 1] = pack_bf(va.z, va.w);
            Al[rr * LDSR + pc]     = pack_bf(bf_res(va.x), bf_res(va.y));
            Al[rr * LDSR + pc + 1] = pack_bf(bf_res(va.z), bf_res(va.w));
            Bs[rr * LDSR + pc]     = pack_bf(vb.x, vb.y);
            Bs[rr * LDSR + pc + 1] = pack_bf(vb.z, vb.w);
            Bl[rr * LDSR + pc]     = pack_bf(bf_res(vb.x), bf_res(vb.y));
            Bl[rr * LDSR + pc + 1] = pack_bf(bf_res(vb.z), bf_res(vb.w));
        }
        __syncthreads();
#pragma unroll
        for (int ks = 0; ks < 2; ks++) {
            int kp = ks * 8;
            uint32_t a[2][4], al[2][4];
#pragma unroll
            for (int i = 0; i < 2; i++) {
                int ro = (wm * 32 + i * 16 + grp) * LDSR + kp + tq;
                a[i][0] = As[ro];
                a[i][1] = As[ro + 8 * LDSR];
                a[i][2] = As[ro + 4];
                a[i][3] = As[ro + 8 * LDSR + 4];
                al[i][0] = Al[ro];
                al[i][1] = Al[ro + 8 * LDSR];
                al[i][2] = Al[ro + 4];
                al[i][3] = Al[ro + 8 * LDSR + 4];
            }
#pragma unroll
            for (int j = 0; j < 8; j++) {
                int co = (wn * 64 + j * 8 + grp) * LDSR + kp + tq;
                uint32_t b[2], bl2[2];
                b[0] = Bs[co];
                b[1] = Bs[co + 4];
                bl2[0] = Bl[co];
                bl2[1] = Bl[co + 4];
#pragma unroll
                for (int i = 0; i < 2; i++) {
                    MMA16B(acc[i][j], al[i], b);
                    MMA16B(acc[i][j], a[i], bl2);
                    MMA16B(acc[i][j], a[i], b);
                }
            }
        }
    }

    const float SC = SCALE ? 1.4426950408889634f : 1.0f;  // log2(e) for softmax folding
    int row0 = blockIdx.x * BM + wm * 32 + grp;
    int col0 = blockIdx.y * 128 + wn * 64 + 2 * tq;
#pragma unroll
    for (int i = 0; i < 2; i++) {
#pragma unroll
        for (int j = 0; j < 8; j++) {
            int row = row0 + i * 16;
            int col = col0 + j * 8;
            float2 bb = *(const float2*)(bias + col);
            float2 v0 = make_float2((acc[i][j][0] + bb.x) * SC, (acc[i][j][1] + bb.y) * SC);
            float2 v1 = make_float2((acc[i][j][2] + bb.x) * SC, (acc[i][j][3] + bb.y) * SC);
            if (OUT == 1 || (OUT == 2 && col < 256)) {
                int pr = (OUT == 1) ? (Ncols >> 1) : 128;
                long long i0 = (long long)row * pr + (col >> 1);
                long long i1 = (long long)(row + 8) * pr + (col >> 1);
                Chi[i0] = pack_bf(v0.x, v0.y);
                Clo[i0] = pack_bf(bf_res(v0.x), bf_res(v0.y));
                Chi[i1] = pack_bf(v1.x, v1.y);
                Clo[i1] = pack_bf(bf_res(v1.x), bf_res(v1.y));
            } else {
                int gc = col - 256;
                *(float2*)(Cg + (long long)row * 256 + gc) = v0;
                *(float2*)(Cg + (long long)(row + 8) * 256 + gc) = v1;
            }
        }
    }
}

// ---------------- fused scores+softmax+out (R15 + mt-boundary prefetch) ---------------
__global__ void __launch_bounds__(256, 1)
fused_attn(const uint32_t* __restrict__ Hhi, const uint32_t* __restrict__ Hlo,
           const uint32_t* __restrict__ Lhi, const uint32_t* __restrict__ Llo,
           const uint32_t* __restrict__ Gt,  // fp16 pairs [B,256,512] u32
           const float* __restrict__ p, float* __restrict__ out) {
    constexpr int LDSR = 20, ARR = 128 * LDSR, STAGE = 4 * ARR;
    constexpr int LDG = 68;
    extern __shared__ uint32_t sm[];
    uint32_t* sG = sm + 2 * STAGE;
    uint32_t sbase = (uint32_t)__cvta_generic_to_shared(sm);
    uint32_t gbase = sbase + 2 * STAGE * 4;

    int tid = threadIdx.x;
    int lane = tid & 31, wid = tid >> 5;
    int grp = lane >> 2, tq = lane & 3;
    int bx = blockIdx.x, zb = blockIdx.z;

    const uint32_t* Ah = Hhi + ((long long)zb * NN + bx * 128) * 128;
    const uint32_t* Alg = Hlo + ((long long)zb * NN + bx * 128) * 128;
    const uint32_t* Bh_b = Lhi + (long long)zb * NM * 128;
    const uint32_t* Bl_b = Llo + (long long)zb * NM * 128;
    const uint32_t* Gtb = Gt + (long long)zb * 256 * 512;

    int rr0 = tid >> 2, uc0 = (tid & 3) * 4;
    int rr1 = (tid + 256) >> 2, uc1 = ((tid + 256) & 3) * 4;
    uint32_t o0 = (uint32_t)(rr0 * LDSR + uc0) * 4;
    uint32_t o1 = (uint32_t)(rr1 * LDSR + uc1) * 4;

    // A/B tile chunk of tile `mti`, K-chunk kcp -> stage st (no commit)
    auto issueAB = [&](int st, int mti, int kcp) {
        const uint32_t* Bh = Bh_b + (long long)mti * 128 * 128;
        const uint32_t* Bl = Bl_b + (long long)mti * 128 * 128;
        uint32_t dA = sbase + (uint32_t)st * STAGE * 4;
        uint32_t dB = dA + ARR * 4;
        uint32_t dAl = dA + 2 * ARR * 4;
        uint32_t dBl = dA + 3 * ARR * 4;
        cp16(dA + o0, Ah + (long long)rr0 * 128 + kcp + uc0);
        cp16(dA + o1, Ah + (long long)rr1 * 128 + kcp + uc1);
        cp16(dAl + o0, Alg + (long long)rr0 * 128 + kcp + uc0);
        cp16(dAl + o1, Alg + (long long)rr1 * 128 + kcp + uc1);
        cp16(dB + o0, Bh + (long long)rr0 * 128 + kcp + uc0);
        cp16(dB + o1, Bh + (long long)rr1 * 128 + kcp + uc1);
        cp16(dBl + o0, Bl + (long long)rr0 * 128 + kcp + uc0);
        cp16(dBl + o1, Bl + (long long)rr1 * 128 + kcp + uc1);
    };
    // one GT chunk (512 float4 of the 4096-total tile) for tile mti (no commit)
    auto issueGT = [&](int mti, int ch) {
        int g = ch * 512 + tid * 2;
        int gr = g >> 4, gc = (g & 15) * 4;
        cp16(gbase + (uint32_t)(gr * LDG + gc) * 4, Gtb + (long long)gr * 512 + mti * 64 + gc);
        g++; gr = g >> 4; gc = (g & 15) * 4;
        cp16(gbase + (uint32_t)(gr * LDG + gc) * 4, Gtb + (long long)gr * 512 + mti * 64 + gc);
    };

    float o[32][4];
#pragma unroll
    for (int j = 0; j < 32; j++)
#pragma unroll
        for (int q = 0; q < 4; q++) o[j][q] = 0.f;
    float m0 = -1e30f, m1 = -1e30f, s0 = 0.f, s1 = 0.f;

    // prologue: prefetch mt=0, tile-chunk 0 into stage 0
    issueAB(0, 0, 0);
    asm volatile("cp.async.commit_group;");

    for (int mt = 0; mt < 8; mt++) {
        float c[16][4];
#pragma unroll
        for (int j = 0; j < 16; j++)
#pragma unroll
            for (int q = 0; q < 4; q++) c[j][q] = 0.f;

        // ---- phase A: 8 K-chunks; chunk t prefetched by previous iter/boundary ----
        for (int t = 0; t < 8; t++) {
            if (t + 1 < 8) {
                issueAB((t + 1) & 1, mt, (t + 1) * 16);
                // GT chunks ride in-loop issues: first issue carries ch0+ch1
                issueGT(mt, t + 1);
                if (t == 0) issueGT(mt, 0);
                asm volatile("cp.async.commit_group;");
                asm volatile("cp.async.wait_group 1;");
            } else {
                asm volatile("cp.async.wait_group 0;");
            }
            __syncthreads();
            const uint32_t* As = sm + (t & 1) * STAGE;
            const uint32_t* Bs = As + ARR;
            const uint32_t* Al = As + 2 * ARR;
            const uint32_t* Blo2 = As + 3 * ARR;
#pragma unroll
            for (int ks = 0; ks < 2; ks++) {
                int kp = ks * 8;
                uint32_t a[4], al[4];
                int ro = (wid * 16 + grp) * LDSR + kp + tq;
                a[0] = As[ro];
                a[1] = As[ro + 8 * LDSR];
                a[2] = As[ro + 4];
                a[3] = As[ro + 8 * LDSR + 4];
                al[0] = Al[ro];
                al[1] = Al[ro + 8 * LDSR];
                al[2] = Al[ro + 4];
                al[3] = Al[ro + 8 * LDSR + 4];
#pragma unroll
                for (int j = 0; j < 16; j++) {
                    int co = (j * 8 + grp) * LDSR + kp + tq;
                    uint32_t b[2], bl2[2];
                    b[0] = Bs[co];
                    b[1] = Bs[co + 4];
                    bl2[0] = Blo2[co];
                    bl2[1] = Blo2[co + 4];
                    MMA16B(c[j], al, b);
                    MMA16B(c[j], a, bl2);
                    MMA16B(c[j], a, b);
                }
            }
        }
        __syncthreads();  // all warps done with both stages before boundary prefetch

        // ---- boundary prefetch: next tile's chunk 0 -> stage 0 (covered by B+C) ----
        if (mt + 1 < 8) {
            issueAB(0, mt + 1, 0);
            asm volatile("cp.async.commit_group;");
        }

        // ---- phase B: online softmax (quad-local), exp2 domain ----
        float mx0 = -1e30f, mx1 = -1e30f;
#pragma unroll
        for (int j = 0; j < 16; j++) {
            mx0 = fmaxf(mx0, fmaxf(c[j][0], c[j][1]));
            mx1 = fmaxf(mx1, fmaxf(c[j][2], c[j][3]));
        }
        mx0 = fmaxf(mx0, __shfl_xor_sync(0xffffffffu, mx0, 1));
        mx0 = fmaxf(mx0, __shfl_xor_sync(0xffffffffu, mx0, 2));
        mx1 = fmaxf(mx1, __shfl_xor_sync(0xffffffffu, mx1, 1));
        mx1 = fmaxf(mx1, __shfl_xor_sync(0xffffffffu, mx1, 2));
        float nm0 = fmaxf(m0, mx0), nm1 = fmaxf(m1, mx1);
        float sc0 = exp2f(m0 - nm0), sc1 = exp2f(m1 - nm1);
        m0 = nm0; m1 = nm1;
        s0 *= sc0; s1 *= sc1;
        if (sc0 != 1.0f || sc1 != 1.0f) {
#pragma unroll
            for (int j = 0; j < 32; j++) {
                o[j][0] *= sc0; o[j][1] *= sc0;
                o[j][2] *= sc1; o[j][3] *= sc1;
            }
        }
#pragma unroll
        for (int j = 0; j < 16; j++) {
            c[j][0] = exp2f(c[j][0] - m0);
            c[j][1] = exp2f(c[j][1] - m0);
            c[j][2] = exp2f(c[j][2] - m1);
            c[j][3] = exp2f(c[j][3] - m1);
            s0 += c[j][0] + c[j][1];
            s1 += c[j][2] + c[j][3];
        }

        // ---- phase C: out += attn @ GT (attn from registers) ----
#pragma unroll
        for (int kt = 0; kt < 8; kt++) {
            uint32_t a[4];
            a[0] = pack_hf(c[2 * kt][0], c[2 * kt][1]);
            a[1] = pack_hf(c[2 * kt][2], c[2 * kt][3]);
            a[2] = pack_hf(c[2 * kt + 1][0], c[2 * kt + 1][1]);
            a[3] = pack_hf(c[2 * kt + 1][2], c[2 * kt + 1][3]);
#pragma unroll
            for (int j = 0; j < 32; j++) {
                int co = (j * 8 + grp) * LDG + kt * 8 + tq;
                uint32_t b[2];
                b[0] = sG[co];
                b[1] = sG[co + 4];
                MMA16H(o[j], a, b);
            }
        }
        __syncthreads();  // sG reads done before next tile's GT writes
    }

    // ---- epilogue: normalize, residual, store ----
    s0 += __shfl_xor_sync(0xffffffffu, s0, 1);
    s0 += __shfl_xor_sync(0xffffffffu, s0, 2);
    s1 += __shfl_xor_sync(0xffffffffu, s1, 1);
    s1 += __shfl_xor_sync(0xffffffffu, s1, 2);
    float inv0 = 1.0f / s0, inv1 = 1.0f / s1;

    int r0 = bx * 128 + wid * 16 + grp;
    float* ob = out + ((long long)zb * NN + r0) * ND;
    const float* pb = p + ((long long)zb * NN + r0) * ND;
#pragma unroll
    for (int j = 0; j < 32; j++) {
        int col = j * 8 + 2 * tq;
        float2 v0 = make_float2(o[j][0] * inv0 + pb[col], o[j][1] * inv0 + pb[col + 1]);
        float2 v1 = make_float2(o[j][2] * inv1 + pb[8 * ND + col],
                                o[j][3] * inv1 + pb[8 * ND + col + 1]);
        *(float2*)(ob + col) = v0;
        *(float2*)(ob + 8 * ND + col) = v1;
    }
}

extern "C" void kernel_launch(void* const* d_in, const int* in_sizes, int n_in,
                              void* d_out, int out_size) {
    const float* p  = (const float*)d_in[0];
    const float* r  = (const float*)d_in[1];
    const float* Wh = (const float*)d_in[3];
    const float* bh = (const float*)d_in[4];
    const float* Wl = (const float*)d_in[5];
    const float* bl = (const float*)d_in[6];
    const float* Wg = (const float*)d_in[7];
    const float* bg = (const float*)d_in[8];
    float* out = (float*)d_out;
    (void)in_sizes; (void)n_in; (void)out_size;

    float* s = nullptr;
    cudaGetSymbolAddress((void**)&s, g_scratch);
    float* WhT = s + OFF_WHT;
    float* WlT = s + OFF_WLT;
    float* BLG = s + OFF_BLG;
    uint32_t* Hhi = (uint32_t*)(s + OFF_HHI);
    uint32_t* Hlo = (uint32_t*)(s + OFF_HLO);
    uint32_t* Lhi = (uint32_t*)(s + OFF_LHI);
    uint32_t* Llo = (uint32_t*)(s + OFF_LLO);
    float* G = s + OFF_G;
    __half* GTh = (__half*)(s + OFF_GT);

    const int SMEM_BF3 = 4 * 128 * 20 * 4;                       // 40960
    const int SMEM_FUSED = 2 * 4 * 128 * 20 * 4 + 256 * 68 * 4;  // 151552
    cudaFuncSetAttribute(gemm_bf3<1, true>,
                         cudaFuncAttributeMaxDynamicSharedMemorySize, SMEM_BF3);
    cudaFuncSetAttribute(gemm_bf3<2, false>,
                         cudaFuncAttributeMaxDynamicSharedMemorySize, SMEM_BF3);
    cudaFuncSetAttribute(fused_attn,
                         cudaFuncAttributeMaxDynamicSharedMemorySize, SMEM_FUSED);

    // 0. transpose weights; concat biases
    transpose_w_k<<<256, 256>>>(Wh, Wl, Wg, bl, bg, WhT, WlT, WlT + (size_t)ND * ND, BLG);

    // 1. H = (p @ Wh + bh) * log2(e)  -> packed bf16 hi/lo
    gemm_bf3<1, true><<<dim3(NB * NN / 128, ND / 128, 1), 256, SMEM_BF3>>>(
        p, WhT, bh, Hhi, Hlo, nullptr, ND, ND);

    // 2+3. [L | G] = r @ [Wl | Wg] + [bl | bg]  (L packed bf16, G fp32)
    gemm_bf3<2, false><<<dim3(NB * NM / 128, 2 * ND / 128, 1), 256, SMEM_BF3>>>(
        r, WlT, BLG, Lhi, Llo, G, ND, 2 * ND);

    // 4. GT[b][d][m] fp16
    transpose_g_k<<<dim3(NM / 32, ND / 32, NB), dim3(32, 8)>>>(G, GTh);

    // 5. fused: out = p + softmax2(H L^T) @ G
    fused_attn<<<dim3(NN / 128, 1, NB), 256, SMEM_FUSED>>>(
        Hhi, Hlo, Lhi, Llo, (const uint32_t*)GTh, p, out);
}